// round 15
// baseline (speedup 1.0000x reference)
#include <cuda_runtime.h>
#include <cuda_bf16.h>
#include <cstdint>

// Problem constants: N=100000, E=1000000, H=8, C=10, HC=80
#define NN   100000
#define EE   1000000
#define HC   80
#define H    8
#define C    10
#define NBLK ((NN + 1023) / 1024)   // 98 scan blocks

typedef unsigned int u32;

// ---------------- scratch (device globals) -----------------------------------
__device__ float g_xl[(size_t)NN * HC];   // Wl x  (source transform)
__device__ float g_xr[(size_t)NN * HC];   // Wr x  (target transform)
__device__ float g_h[(size_t)NN * HC];    // layer activations (next input)
__device__ int   g_deg[NN];
__device__ int   g_rowptr[NN + 1];
__device__ int   g_cursor[NN];
__device__ int   g_csr[EE];               // src indices grouped by dst
__device__ int   g_bsum[NBLK];            // scan block totals
__device__ int   g_boff[NBLK];            // scan block offsets
// transposed bf16 weights: [layer][hi/lo][n*DIN + k], n in [0,160): Wl|Wr
__device__ __nv_bfloat16 g_wt[3][2][160 * 128];

// ---------------- bf16 split helpers -----------------------------------------
__device__ __forceinline__ void split_bf16(float f, __nv_bfloat16& hi, __nv_bfloat16& lo) {
    hi = __float2bfloat16(f);
    lo = __float2bfloat16(f - __bfloat162float(hi));
}

// HMMA m16n8k16 bf16 -> f32
__device__ __forceinline__ void mma16816(float* d, const u32* a, u32 b0, u32 b1) {
    asm volatile(
        "mma.sync.aligned.m16n8k16.row.col.f32.bf16.bf16.f32 "
        "{%0,%1,%2,%3}, {%4,%5,%6,%7}, {%8,%9}, {%0,%1,%2,%3};"
        : "+f"(d[0]), "+f"(d[1]), "+f"(d[2]), "+f"(d[3])
        : "r"(a[0]), "r"(a[1]), "r"(a[2]), "r"(a[3]), "r"(b0), "r"(b1));
}

// ---------------- W prep: fp32 [K][80] x2 -> k-major hi/lo bf16 [160][K] -----
__global__ void prep_w(const float* __restrict__ Wl, const float* __restrict__ Wr,
                       int K, int layer) {
    int t = blockIdx.x * blockDim.x + threadIdx.x;
    if (t >= 160 * K) return;
    int n = t / K, k = t - n * K;
    float v = (n < 80) ? Wl[k * 80 + n] : Wr[k * 80 + (n - 80)];
    __nv_bfloat16 hi, lo;
    split_bf16(v, hi, lo);
    g_wt[layer][0][n * K + k] = hi;
    g_wt[layer][1][n * K + k] = lo;
}

// ---------------- HMMA GEMM, split-output: CTA = 128 rows x 80 cols ----------
template <int DIN>
__global__ __launch_bounds__(256) void hmma_gemm(
    const float* __restrict__ X, int layer,
    float* __restrict__ Yl, float* __restrict__ Yr, int N) {
    constexpr int SA = DIN + 8;
    constexpr int KS = DIN / 16;
    extern __shared__ char smem[];
    __nv_bfloat16* Ah = (__nv_bfloat16*)smem;
    __nv_bfloat16* Al = Ah + 128 * SA;
    __nv_bfloat16* Bh = Al + 128 * SA;
    __nv_bfloat16* Bl = Bh + 80 * SA;

    const int tid = threadIdx.x;
    const int row0 = blockIdx.x * 128;
    const int half = blockIdx.y;            // 0 = Wl, 1 = Wr
    const int nglob0 = half * 80;

    for (int i = tid; i < 128 * (DIN / 4); i += 256) {
        int r = i / (DIN / 4), kq = i - r * (DIN / 4);
        int gr = row0 + r;
        float4 v = make_float4(0.f, 0.f, 0.f, 0.f);
        if (gr < N) v = *(const float4*)(X + (size_t)gr * DIN + kq * 4);
        __nv_bfloat16 h0, l0, h1, l1, h2, l2, h3, l3;
        split_bf16(v.x, h0, l0); split_bf16(v.y, h1, l1);
        split_bf16(v.z, h2, l2); split_bf16(v.w, h3, l3);
        __nv_bfloat16* ph = Ah + r * SA + kq * 4;
        __nv_bfloat16* pl = Al + r * SA + kq * 4;
        ph[0] = h0; ph[1] = h1; ph[2] = h2; ph[3] = h3;
        pl[0] = l0; pl[1] = l1; pl[2] = l2; pl[3] = l3;
    }
    for (int i = tid; i < 80 * (DIN / 4); i += 256) {
        int n = i / (DIN / 4), kq = i - n * (DIN / 4);
        uint2 vh = *(const uint2*)&g_wt[layer][0][(nglob0 + n) * DIN + kq * 4];
        uint2 vl = *(const uint2*)&g_wt[layer][1][(nglob0 + n) * DIN + kq * 4];
        *(uint2*)&Bh[n * SA + kq * 4] = vh;
        *(uint2*)&Bl[n * SA + kq * 4] = vl;
    }
    __syncthreads();

    const int warp = tid >> 5, lane = tid & 31;
    const int warpM = warp >> 1, warpN = warp & 1;
    const int r0 = warpM * 32, nbase = warpN * 40;
    const int g = lane >> 2, c = lane & 3;

    float acc[2][5][4];
#pragma unroll
    for (int mt = 0; mt < 2; mt++)
#pragma unroll
        for (int nt = 0; nt < 5; nt++)
#pragma unroll
            for (int q = 0; q < 4; q++) acc[mt][nt][q] = 0.f;

    for (int ks = 0; ks < KS; ks++) {
        const int kb = ks * 16;
        u32 ah[2][4], al[2][4];
#pragma unroll
        for (int mt = 0; mt < 2; mt++) {
            int base = (r0 + mt * 16 + g) * SA + kb;
            ah[mt][0] = *(const u32*)&Ah[base + 2 * c];
            ah[mt][1] = *(const u32*)&Ah[base + 8 * SA + 2 * c];
            ah[mt][2] = *(const u32*)&Ah[base + 2 * c + 8];
            ah[mt][3] = *(const u32*)&Ah[base + 8 * SA + 2 * c + 8];
            al[mt][0] = *(const u32*)&Al[base + 2 * c];
            al[mt][1] = *(const u32*)&Al[base + 8 * SA + 2 * c];
            al[mt][2] = *(const u32*)&Al[base + 2 * c + 8];
            al[mt][3] = *(const u32*)&Al[base + 8 * SA + 2 * c + 8];
        }
#pragma unroll
        for (int nt = 0; nt < 5; nt++) {
            int bbase = (nbase + nt * 8 + g) * SA + kb;
            u32 bh0 = *(const u32*)&Bh[bbase + 2 * c];
            u32 bh1 = *(const u32*)&Bh[bbase + 2 * c + 8];
            u32 bl0 = *(const u32*)&Bl[bbase + 2 * c];
            u32 bl1 = *(const u32*)&Bl[bbase + 2 * c + 8];
#pragma unroll
            for (int mt = 0; mt < 2; mt++) {
                mma16816(acc[mt][nt], ah[mt], bh0, bh1);
                mma16816(acc[mt][nt], ah[mt], bl0, bl1);
                mma16816(acc[mt][nt], al[mt], bh0, bh1);
            }
        }
    }

    float* Y = (half == 0) ? Yl : Yr;
#pragma unroll
    for (int mt = 0; mt < 2; mt++) {
        int ga = row0 + r0 + mt * 16 + g;
#pragma unroll
        for (int nt = 0; nt < 5; nt++) {
            int col = nbase + nt * 8 + 2 * c;
            if (ga < N)
                *(float2*)&Y[(size_t)ga * 80 + col] =
                    make_float2(acc[mt][nt][0], acc[mt][nt][1]);
            if (ga + 8 < N)
                *(float2*)&Y[(size_t)(ga + 8) * 80 + col] =
                    make_float2(acc[mt][nt][2], acc[mt][nt][3]);
        }
    }
}

// ---------------- CSR build (parallel 3-kernel scan) --------------------------
__global__ void hist_k(const int* __restrict__ ei) {
    int t = blockIdx.x * blockDim.x + threadIdx.x;
    if (t < EE) atomicAdd(&g_deg[ei[EE + t]], 1);
}

__global__ __launch_bounds__(1024) void pscan1_k() {
    __shared__ int warpsum[32];
    const int tid = threadIdx.x;
    const int lane = tid & 31, wid = tid >> 5;
    int i = blockIdx.x * 1024 + tid;
    int v = (i < NN) ? g_deg[i] : 0;
    int incl = v;
#pragma unroll
    for (int o = 1; o < 32; o <<= 1) {
        int n = __shfl_up_sync(0xffffffffu, incl, o);
        if (lane >= o) incl += n;
    }
    if (lane == 31) warpsum[wid] = incl;
    __syncthreads();
    if (tid < 32) {
        int w = warpsum[tid];
        int wi = w;
#pragma unroll
        for (int o = 1; o < 32; o <<= 1) {
            int n = __shfl_up_sync(0xffffffffu, wi, o);
            if (tid >= o) wi += n;
        }
        warpsum[tid] = wi - w;
    }
    __syncthreads();
    int excl = warpsum[wid] + incl - v;
    if (i < NN) g_rowptr[i] = excl;
    if (tid == 1023) g_bsum[blockIdx.x] = excl + v;
}

__global__ __launch_bounds__(128) void pscan2_k() {
    __shared__ int sh[NBLK];
    int tid = threadIdx.x;
    for (int i = tid; i < NBLK; i += 128) sh[i] = g_bsum[i];
    __syncthreads();
    if (tid == 0) {
        int run = 0;
        for (int i = 0; i < NBLK; i++) { int v = sh[i]; sh[i] = run; run += v; }
    }
    __syncthreads();
    for (int i = tid; i < NBLK; i += 128) g_boff[i] = sh[i];
}

__global__ __launch_bounds__(1024) void pscan3_k() {
    int i = blockIdx.x * 1024 + threadIdx.x;
    if (i < NN) {
        int r = g_rowptr[i] + g_boff[blockIdx.x];
        g_rowptr[i] = r;
        g_cursor[i] = r;
    }
    if (i == 0) g_rowptr[NN] = EE;
}

__global__ void fill_k(const int* __restrict__ ei) {
    int t = blockIdx.x * blockDim.x + threadIdx.x;
    if (t >= EE) return;
    int s = ei[t], d = ei[EE + t];
    int p = atomicAdd(&g_cursor[d], 1);
    g_csr[p] = s;
}

// ---------------- fused attention aggregate (fixed-shift, 2 lanes/(d,h)) -----
// Fixed shift m = self-loop logit -> partial sums are associative; lanes
// (2q, 2q+1) split the edge list and combine with one shfl_xor.
__global__ __launch_bounds__(256) void agg_k(const float* __restrict__ att,
                                             const float* __restrict__ bias,
                                             float* __restrict__ out) {
    int t = blockIdx.x * blockDim.x + threadIdx.x;
    if (t >= NN * H * 2) return;
    int q = t >> 1, half = t & 1;
    int d = q >> 3, h = q & 7;

    float xr_[10], at[10];
    {
        const float2* xrp = (const float2*)(g_xr + (size_t)d * HC + h * C);
        const float2* atp = (const float2*)(att + h * C);
#pragma unroll
        for (int i = 0; i < 5; i++) {
            float2 a = __ldg(xrp + i);
            xr_[2 * i] = a.x; xr_[2 * i + 1] = a.y;
            float2 w = __ldg(atp + i);
            at[2 * i] = w.x; at[2 * i + 1] = w.y;
        }
    }

    // self loop: both halves compute the shift m; only half 0 seeds the sums
    float acc[10];
    float m, ssum;
    {
        const float2* xsp = (const float2*)(g_xl + (size_t)d * HC + h * C);
        float e = 0.f;
#pragma unroll
        for (int i = 0; i < 5; i++) {
            float2 a = __ldg(xsp + i);
            float sx = (half == 0) ? a.x : 0.f;
            float sy = (half == 0) ? a.y : 0.f;
            acc[2 * i] = sx; acc[2 * i + 1] = sy;
            float v0 = a.x + xr_[2 * i];     v0 = v0 > 0.f ? v0 : 0.2f * v0;
            float v1 = a.y + xr_[2 * i + 1]; v1 = v1 > 0.f ? v1 : 0.2f * v1;
            e += at[2 * i] * v0 + at[2 * i + 1] * v1;
        }
        m = e;
        ssum = (half == 0) ? 1.f : 0.f;
    }

    const int beg = __ldg(&g_rowptr[d]);
    const int end = __ldg(&g_rowptr[d + 1]);

    // this half's strided edge walk with one-ahead prefetch
    int j = beg + half;
    float nx[10];
    if (j < end) {
        const float2* p = (const float2*)(g_xl + (size_t)__ldg(&g_csr[j]) * HC + h * C);
#pragma unroll
        for (int i = 0; i < 5; i++) {
            float2 a = __ldg(p + i);
            nx[2 * i] = a.x; nx[2 * i + 1] = a.y;
        }
    }
    for (; j < end; j += 2) {
        float xs_[10];
#pragma unroll
        for (int cc = 0; cc < 10; cc++) xs_[cc] = nx[cc];
        if (j + 2 < end) {
            const float2* p = (const float2*)(g_xl + (size_t)__ldg(&g_csr[j + 2]) * HC + h * C);
#pragma unroll
            for (int i = 0; i < 5; i++) {
                float2 a = __ldg(p + i);
                nx[2 * i] = a.x; nx[2 * i + 1] = a.y;
            }
        }
        float e = 0.f;
#pragma unroll
        for (int i = 0; i < 5; i++) {
            float v0 = xs_[2 * i] + xr_[2 * i];         v0 = v0 > 0.f ? v0 : 0.2f * v0;
            float v1 = xs_[2 * i + 1] + xr_[2 * i + 1]; v1 = v1 > 0.f ? v1 : 0.2f * v1;
            e += at[2 * i] * v0 + at[2 * i + 1] * v1;
        }
        float p = __expf(e - m);
        ssum += p;
#pragma unroll
        for (int cc = 0; cc < 10; cc++) acc[cc] = fmaf(p, xs_[cc], acc[cc]);
    }

    // combine the two halves (adjacent lanes)
    ssum += __shfl_xor_sync(0xffffffffu, ssum, 1);
#pragma unroll
    for (int cc = 0; cc < 10; cc++)
        acc[cc] += __shfl_xor_sync(0xffffffffu, acc[cc], 1);

    if (half == 0) {
        float inv = 1.f / ssum;
        float2* op = (float2*)(out + (size_t)d * HC + h * C);
#pragma unroll
        for (int i = 0; i < 5; i++) {
            float b0 = __ldg(bias + h * C + 2 * i);
            float b1 = __ldg(bias + h * C + 2 * i + 1);
            float v0 = acc[2 * i] * inv + b0;
            float v1 = acc[2 * i + 1] * inv + b1;
            v0 = v0 > 0.f ? v0 : expm1f(v0);
            v1 = v1 > 0.f ? v1 : expm1f(v1);
            op[i] = make_float2(v0, v1);
        }
    }
}

// ---------------- launch -----------------------------------------------------
extern "C" void kernel_launch(void* const* d_in, const int* in_sizes, int n_in,
                              void* d_out, int out_size) {
    const float* x  = (const float*)d_in[0];
    const int*   ei = (const int*)d_in[1];
    const float* Wl[3]  = {(const float*)d_in[2], (const float*)d_in[6], (const float*)d_in[10]};
    const float* Wr[3]  = {(const float*)d_in[3], (const float*)d_in[7], (const float*)d_in[11]};
    const float* att[3] = {(const float*)d_in[4], (const float*)d_in[8], (const float*)d_in[12]};
    const float* bs[3]  = {(const float*)d_in[5], (const float*)d_in[9], (const float*)d_in[13]};

    const int N = NN;

    float *p_xl, *p_xr, *p_h;
    int* p_deg;
    cudaGetSymbolAddress((void**)&p_xl, g_xl);
    cudaGetSymbolAddress((void**)&p_xr, g_xr);
    cudaGetSymbolAddress((void**)&p_h, g_h);
    cudaGetSymbolAddress((void**)&p_deg, g_deg);

    // ---- CSR build + weight prep (once) ----
    cudaMemsetAsync(p_deg, 0, (size_t)NN * sizeof(int));
    hist_k<<<(EE + 255) / 256, 256>>>(ei);
    pscan1_k<<<NBLK, 1024>>>();
    pscan2_k<<<1, 128>>>();
    pscan3_k<<<NBLK, 1024>>>();
    fill_k<<<(EE + 255) / 256, 256>>>(ei);
    for (int l = 0; l < 3; l++) {
        int K = (l == 0) ? 128 : 80;
        prep_w<<<(160 * K + 255) / 256, 256>>>(Wl[l], Wr[l], K, l);
    }

    const int smem128 = (2 * 128 + 2 * 80) * 136 * 2;  // 113152 -> 2 CTAs/SM
    const int smem80  = (2 * 128 + 2 * 80) * 88 * 2;   //  73216 -> 3 CTAs/SM
    cudaFuncSetAttribute(hmma_gemm<128>, cudaFuncAttributeMaxDynamicSharedMemorySize, smem128);
    cudaFuncSetAttribute(hmma_gemm<80>,  cudaFuncAttributeMaxDynamicSharedMemorySize, smem80);

    const dim3 gemmGrid((N + 127) / 128, 2);
    const int aggBlocks = (NN * H * 2 + 255) / 256;

    const float* xin = x;
    for (int l = 0; l < 3; l++) {
        if (l == 0)
            hmma_gemm<128><<<gemmGrid, 256, smem128>>>(xin, l, p_xl, p_xr, N);
        else
            hmma_gemm<80><<<gemmGrid, 256, smem80>>>(xin, l, p_xl, p_xr, N);
        float* xout = (l == 2) ? (float*)d_out : p_h;
        agg_k<<<aggBlocks, 256>>>(att[l], bs[l], xout);
        xin = p_h;
    }
}

// round 16
// speedup vs baseline: 1.1781x; 1.1781x over previous
#include <cuda_runtime.h>
#include <cuda_bf16.h>
#include <cstdint>

// Problem constants: N=100000, E=1000000, H=8, C=10, HC=80
#define NN   100000
#define EE   1000000
#define HC   80
#define H    8
#define C    10
#define NBLK ((NN + 1023) / 1024)   // 98 scan blocks

typedef unsigned int u32;

// ---------------- scratch (device globals) -----------------------------------
__device__ float g_xl[(size_t)NN * HC];   // Wl x  (source transform)
__device__ float g_xr[(size_t)NN * HC];   // Wr x  (target transform)
__device__ float g_h[(size_t)NN * HC];    // layer activations (next input)
__device__ int   g_deg[NN];
__device__ int   g_rowptr[NN + 1];
__device__ int   g_cursor[NN];
__device__ int   g_csr[EE];               // src indices grouped by dst
__device__ int   g_bsum[NBLK];            // scan block totals
__device__ int   g_boff[NBLK];            // scan block offsets
// transposed bf16 weights: [layer][hi/lo][n*DIN + k], n in [0,160): Wl|Wr
__device__ __nv_bfloat16 g_wt[3][2][160 * 128];

// ---------------- bf16 split helpers -----------------------------------------
__device__ __forceinline__ void split_bf16(float f, __nv_bfloat16& hi, __nv_bfloat16& lo) {
    hi = __float2bfloat16(f);
    lo = __float2bfloat16(f - __bfloat162float(hi));
}

// HMMA m16n8k16 bf16 -> f32
__device__ __forceinline__ void mma16816(float* d, const u32* a, u32 b0, u32 b1) {
    asm volatile(
        "mma.sync.aligned.m16n8k16.row.col.f32.bf16.bf16.f32 "
        "{%0,%1,%2,%3}, {%4,%5,%6,%7}, {%8,%9}, {%0,%1,%2,%3};"
        : "+f"(d[0]), "+f"(d[1]), "+f"(d[2]), "+f"(d[3])
        : "r"(a[0]), "r"(a[1]), "r"(a[2]), "r"(a[3]), "r"(b0), "r"(b1));
}

// ---------------- W prep: fp32 [K][80] x2 -> k-major hi/lo bf16 [160][K] -----
__global__ void prep_w(const float* __restrict__ Wl, const float* __restrict__ Wr,
                       int K, int layer) {
    int t = blockIdx.x * blockDim.x + threadIdx.x;
    if (t >= 160 * K) return;
    int n = t / K, k = t - n * K;
    float v = (n < 80) ? Wl[k * 80 + n] : Wr[k * 80 + (n - 80)];
    __nv_bfloat16 hi, lo;
    split_bf16(v, hi, lo);
    g_wt[layer][0][n * K + k] = hi;
    g_wt[layer][1][n * K + k] = lo;
}

// ---------------- HMMA GEMM, split-output: CTA = 128 rows x 80 cols ----------
template <int DIN>
__global__ __launch_bounds__(256) void hmma_gemm(
    const float* __restrict__ X, int layer,
    float* __restrict__ Yl, float* __restrict__ Yr, int N) {
    constexpr int SA = DIN + 8;
    constexpr int KS = DIN / 16;
    extern __shared__ char smem[];
    __nv_bfloat16* Ah = (__nv_bfloat16*)smem;
    __nv_bfloat16* Al = Ah + 128 * SA;
    __nv_bfloat16* Bh = Al + 128 * SA;
    __nv_bfloat16* Bl = Bh + 80 * SA;

    const int tid = threadIdx.x;
    const int row0 = blockIdx.x * 128;
    const int half = blockIdx.y;            // 0 = Wl, 1 = Wr
    const int nglob0 = half * 80;

    for (int i = tid; i < 128 * (DIN / 4); i += 256) {
        int r = i / (DIN / 4), kq = i - r * (DIN / 4);
        int gr = row0 + r;
        float4 v = make_float4(0.f, 0.f, 0.f, 0.f);
        if (gr < N) v = *(const float4*)(X + (size_t)gr * DIN + kq * 4);
        __nv_bfloat16 h0, l0, h1, l1, h2, l2, h3, l3;
        split_bf16(v.x, h0, l0); split_bf16(v.y, h1, l1);
        split_bf16(v.z, h2, l2); split_bf16(v.w, h3, l3);
        __nv_bfloat16* ph = Ah + r * SA + kq * 4;
        __nv_bfloat16* pl = Al + r * SA + kq * 4;
        ph[0] = h0; ph[1] = h1; ph[2] = h2; ph[3] = h3;
        pl[0] = l0; pl[1] = l1; pl[2] = l2; pl[3] = l3;
    }
    for (int i = tid; i < 80 * (DIN / 4); i += 256) {
        int n = i / (DIN / 4), kq = i - n * (DIN / 4);
        uint2 vh = *(const uint2*)&g_wt[layer][0][(nglob0 + n) * DIN + kq * 4];
        uint2 vl = *(const uint2*)&g_wt[layer][1][(nglob0 + n) * DIN + kq * 4];
        *(uint2*)&Bh[n * SA + kq * 4] = vh;
        *(uint2*)&Bl[n * SA + kq * 4] = vl;
    }
    __syncthreads();

    const int warp = tid >> 5, lane = tid & 31;
    const int warpM = warp >> 1, warpN = warp & 1;
    const int r0 = warpM * 32, nbase = warpN * 40;
    const int g = lane >> 2, c = lane & 3;

    float acc[2][5][4];
#pragma unroll
    for (int mt = 0; mt < 2; mt++)
#pragma unroll
        for (int nt = 0; nt < 5; nt++)
#pragma unroll
            for (int q = 0; q < 4; q++) acc[mt][nt][q] = 0.f;

    for (int ks = 0; ks < KS; ks++) {
        const int kb = ks * 16;
        u32 ah[2][4], al[2][4];
#pragma unroll
        for (int mt = 0; mt < 2; mt++) {
            int base = (r0 + mt * 16 + g) * SA + kb;
            ah[mt][0] = *(const u32*)&Ah[base + 2 * c];
            ah[mt][1] = *(const u32*)&Ah[base + 8 * SA + 2 * c];
            ah[mt][2] = *(const u32*)&Ah[base + 2 * c + 8];
            ah[mt][3] = *(const u32*)&Ah[base + 8 * SA + 2 * c + 8];
            al[mt][0] = *(const u32*)&Al[base + 2 * c];
            al[mt][1] = *(const u32*)&Al[base + 8 * SA + 2 * c];
            al[mt][2] = *(const u32*)&Al[base + 2 * c + 8];
            al[mt][3] = *(const u32*)&Al[base + 8 * SA + 2 * c + 8];
        }
#pragma unroll
        for (int nt = 0; nt < 5; nt++) {
            int bbase = (nbase + nt * 8 + g) * SA + kb;
            u32 bh0 = *(const u32*)&Bh[bbase + 2 * c];
            u32 bh1 = *(const u32*)&Bh[bbase + 2 * c + 8];
            u32 bl0 = *(const u32*)&Bl[bbase + 2 * c];
            u32 bl1 = *(const u32*)&Bl[bbase + 2 * c + 8];
#pragma unroll
            for (int mt = 0; mt < 2; mt++) {
                mma16816(acc[mt][nt], ah[mt], bh0, bh1);
                mma16816(acc[mt][nt], ah[mt], bl0, bl1);
                mma16816(acc[mt][nt], al[mt], bh0, bh1);
            }
        }
    }

    float* Y = (half == 0) ? Yl : Yr;
#pragma unroll
    for (int mt = 0; mt < 2; mt++) {
        int ga = row0 + r0 + mt * 16 + g;
#pragma unroll
        for (int nt = 0; nt < 5; nt++) {
            int col = nbase + nt * 8 + 2 * c;
            if (ga < N)
                *(float2*)&Y[(size_t)ga * 80 + col] =
                    make_float2(acc[mt][nt][0], acc[mt][nt][1]);
            if (ga + 8 < N)
                *(float2*)&Y[(size_t)(ga + 8) * 80 + col] =
                    make_float2(acc[mt][nt][2], acc[mt][nt][3]);
        }
    }
}

// ---------------- CSR build (parallel 3-kernel scan) --------------------------
__global__ void hist_k(const int* __restrict__ ei) {
    int t = blockIdx.x * blockDim.x + threadIdx.x;
    if (t < EE) atomicAdd(&g_deg[ei[EE + t]], 1);
}

__global__ __launch_bounds__(1024) void pscan1_k() {
    __shared__ int warpsum[32];
    const int tid = threadIdx.x;
    const int lane = tid & 31, wid = tid >> 5;
    int i = blockIdx.x * 1024 + tid;
    int v = (i < NN) ? g_deg[i] : 0;
    int incl = v;
#pragma unroll
    for (int o = 1; o < 32; o <<= 1) {
        int n = __shfl_up_sync(0xffffffffu, incl, o);
        if (lane >= o) incl += n;
    }
    if (lane == 31) warpsum[wid] = incl;
    __syncthreads();
    if (tid < 32) {
        int w = warpsum[tid];
        int wi = w;
#pragma unroll
        for (int o = 1; o < 32; o <<= 1) {
            int n = __shfl_up_sync(0xffffffffu, wi, o);
            if (tid >= o) wi += n;
        }
        warpsum[tid] = wi - w;
    }
    __syncthreads();
    int excl = warpsum[wid] + incl - v;
    if (i < NN) g_rowptr[i] = excl;
    if (tid == 1023) g_bsum[blockIdx.x] = excl + v;
}

__global__ __launch_bounds__(128) void pscan2_k() {
    __shared__ int sh[NBLK];
    int tid = threadIdx.x;
    for (int i = tid; i < NBLK; i += 128) sh[i] = g_bsum[i];
    __syncthreads();
    if (tid == 0) {
        int run = 0;
        for (int i = 0; i < NBLK; i++) { int v = sh[i]; sh[i] = run; run += v; }
    }
    __syncthreads();
    for (int i = tid; i < NBLK; i += 128) g_boff[i] = sh[i];
}

__global__ __launch_bounds__(1024) void pscan3_k() {
    int i = blockIdx.x * 1024 + threadIdx.x;
    if (i < NN) {
        int r = g_rowptr[i] + g_boff[blockIdx.x];
        g_rowptr[i] = r;
        g_cursor[i] = r;
    }
    if (i == 0) g_rowptr[NN] = EE;
}

__global__ void fill_k(const int* __restrict__ ei) {
    int t = blockIdx.x * blockDim.x + threadIdx.x;
    if (t >= EE) return;
    int s = ei[t], d = ei[EE + t];
    int p = atomicAdd(&g_cursor[d], 1);
    g_csr[p] = s;
}

// ---------------- fused attention aggregate (online softmax, pipelined) ------
__global__ __launch_bounds__(256) void agg_k(const float* __restrict__ att,
                                             const float* __restrict__ bias,
                                             float* __restrict__ out) {
    int t = blockIdx.x * blockDim.x + threadIdx.x;
    if (t >= NN * H) return;
    int d = t >> 3, h = t & 7;

    float xr_[10], at[10];
    {
        const float2* xrp = (const float2*)(g_xr + (size_t)d * HC + h * C);
        const float2* atp = (const float2*)(att + h * C);
#pragma unroll
        for (int i = 0; i < 5; i++) {
            float2 a = __ldg(xrp + i);
            xr_[2 * i] = a.x; xr_[2 * i + 1] = a.y;
            float2 w = __ldg(atp + i);
            at[2 * i] = w.x; at[2 * i + 1] = w.y;
        }
    }

    float acc[10];
    float m, ssum = 1.f;
    {
        const float2* xsp = (const float2*)(g_xl + (size_t)d * HC + h * C);
        float e = 0.f;
#pragma unroll
        for (int i = 0; i < 5; i++) {
            float2 a = __ldg(xsp + i);
            acc[2 * i] = a.x; acc[2 * i + 1] = a.y;
            float v0 = a.x + xr_[2 * i];     v0 = v0 > 0.f ? v0 : 0.2f * v0;
            float v1 = a.y + xr_[2 * i + 1]; v1 = v1 > 0.f ? v1 : 0.2f * v1;
            e += at[2 * i] * v0 + at[2 * i + 1] * v1;
        }
        m = e;
    }

    const int beg = __ldg(&g_rowptr[d]);
    const int end = __ldg(&g_rowptr[d + 1]);

    float nx[10];
    if (beg < end) {
        int s0 = __ldg(&g_csr[beg]);
        const float2* p = (const float2*)(g_xl + (size_t)s0 * HC + h * C);
#pragma unroll
        for (int i = 0; i < 5; i++) {
            float2 a = __ldg(p + i);
            nx[2 * i] = a.x; nx[2 * i + 1] = a.y;
        }
    }
    for (int j = beg; j < end; j++) {
        float xs_[10];
#pragma unroll
        for (int cc = 0; cc < 10; cc++) xs_[cc] = nx[cc];
        if (j + 1 < end) {
            int s2 = __ldg(&g_csr[j + 1]);
            const float2* p = (const float2*)(g_xl + (size_t)s2 * HC + h * C);
#pragma unroll
            for (int i = 0; i < 5; i++) {
                float2 a = __ldg(p + i);
                nx[2 * i] = a.x; nx[2 * i + 1] = a.y;
            }
        }
        float e = 0.f;
#pragma unroll
        for (int i = 0; i < 5; i++) {
            float v0 = xs_[2 * i] + xr_[2 * i];         v0 = v0 > 0.f ? v0 : 0.2f * v0;
            float v1 = xs_[2 * i + 1] + xr_[2 * i + 1]; v1 = v1 > 0.f ? v1 : 0.2f * v1;
            e += at[2 * i] * v0 + at[2 * i + 1] * v1;
        }
        if (e <= m) {
            float p = __expf(e - m);
            ssum += p;
#pragma unroll
            for (int cc = 0; cc < 10; cc++) acc[cc] += p * xs_[cc];
        } else {
            float r = __expf(m - e);
            ssum = ssum * r + 1.f;
#pragma unroll
            for (int cc = 0; cc < 10; cc++) acc[cc] = acc[cc] * r + xs_[cc];
            m = e;
        }
    }

    float inv = 1.f / ssum;
    float2* op = (float2*)(out + (size_t)d * HC + h * C);
#pragma unroll
    for (int i = 0; i < 5; i++) {
        float b0 = __ldg(bias + h * C + 2 * i);
        float b1 = __ldg(bias + h * C + 2 * i + 1);
        float v0 = acc[2 * i] * inv + b0;
        float v1 = acc[2 * i + 1] * inv + b1;
        v0 = v0 > 0.f ? v0 : expm1f(v0);
        v1 = v1 > 0.f ? v1 : expm1f(v1);
        op[i] = make_float2(v0, v1);
    }
}

// ---------------- launch -----------------------------------------------------
extern "C" void kernel_launch(void* const* d_in, const int* in_sizes, int n_in,
                              void* d_out, int out_size) {
    const float* x  = (const float*)d_in[0];
    const int*   ei = (const int*)d_in[1];
    const float* Wl[3]  = {(const float*)d_in[2], (const float*)d_in[6], (const float*)d_in[10]};
    const float* Wr[3]  = {(const float*)d_in[3], (const float*)d_in[7], (const float*)d_in[11]};
    const float* att[3] = {(const float*)d_in[4], (const float*)d_in[8], (const float*)d_in[12]};
    const float* bs[3]  = {(const float*)d_in[5], (const float*)d_in[9], (const float*)d_in[13]};

    const int N = NN;

    float *p_xl, *p_xr, *p_h;
    int* p_deg;
    cudaGetSymbolAddress((void**)&p_xl, g_xl);
    cudaGetSymbolAddress((void**)&p_xr, g_xr);
    cudaGetSymbolAddress((void**)&p_h, g_h);
    cudaGetSymbolAddress((void**)&p_deg, g_deg);

    // lazy host-side resources (same captured work every call)
    static cudaStream_t s2 = nullptr;
    static cudaEvent_t ev_fork = nullptr, ev_join = nullptr;
    if (!s2) {
        cudaStreamCreateWithFlags(&s2, cudaStreamNonBlocking);
        cudaEventCreateWithFlags(&ev_fork, cudaEventDisableTiming);
        cudaEventCreateWithFlags(&ev_join, cudaEventDisableTiming);
    }

    // ---- fork: CSR build chain on s2 (only agg needs it) ----
    cudaEventRecord(ev_fork, 0);
    cudaStreamWaitEvent(s2, ev_fork, 0);
    cudaMemsetAsync(p_deg, 0, (size_t)NN * sizeof(int), s2);
    hist_k<<<(EE + 255) / 256, 256, 0, s2>>>(ei);
    pscan1_k<<<NBLK, 1024, 0, s2>>>();
    pscan2_k<<<1, 128, 0, s2>>>();
    pscan3_k<<<NBLK, 1024, 0, s2>>>();
    fill_k<<<(EE + 255) / 256, 256, 0, s2>>>(ei);
    cudaEventRecord(ev_join, s2);

    // ---- main stream: weight prep (gemm dependency) ----
    for (int l = 0; l < 3; l++) {
        int K = (l == 0) ? 128 : 80;
        prep_w<<<(160 * K + 255) / 256, 256>>>(Wl[l], Wr[l], K, l);
    }

    const int smem128 = (2 * 128 + 2 * 80) * 136 * 2;  // 113152 -> 2 CTAs/SM
    const int smem80  = (2 * 128 + 2 * 80) * 88 * 2;   //  73216 -> 3 CTAs/SM
    cudaFuncSetAttribute(hmma_gemm<128>, cudaFuncAttributeMaxDynamicSharedMemorySize, smem128);
    cudaFuncSetAttribute(hmma_gemm<80>,  cudaFuncAttributeMaxDynamicSharedMemorySize, smem80);

    const dim3 gemmGrid((N + 127) / 128, 2);
    const int aggBlocks = (NN * H + 255) / 256;

    const float* xin = x;
    for (int l = 0; l < 3; l++) {
        if (l == 0)
            hmma_gemm<128><<<gemmGrid, 256, smem128>>>(xin, l, p_xl, p_xr, N);
        else
            hmma_gemm<80><<<gemmGrid, 256, smem80>>>(xin, l, p_xl, p_xr, N);
        if (l == 0) cudaStreamWaitEvent(0, ev_join, 0);   // join: agg needs CSR
        float* xout = (l == 2) ? (float*)d_out : p_h;
        agg_k<<<aggBlocks, 256>>>(att[l], bs[l], xout);
        xin = p_h;
    }
}

// round 17
// speedup vs baseline: 1.2044x; 1.0224x over previous
#include <cuda_runtime.h>
#include <cuda_bf16.h>
#include <cstdint>

// Problem constants: N=100000, E=1000000, H=8, C=10, HC=80
#define NN   100000
#define EE   1000000
#define HC   80
#define H    8
#define C    10
#define NBLK ((NN + 1023) / 1024)   // 98 scan blocks

typedef unsigned int u32;

// ---------------- scratch (device globals) -----------------------------------
__device__ float g_xl[(size_t)NN * HC];   // Wl x  (source transform)
__device__ float g_xr[(size_t)NN * HC];   // Wr x  (target transform)
__device__ float g_h[(size_t)NN * HC];    // layer activations (next input)
__device__ int   g_deg[NN];
__device__ int   g_rowptr[NN + 1];
__device__ int   g_cursor[NN];
__device__ int   g_csr[EE];               // src indices grouped by dst
__device__ int   g_bsum[NBLK];            // scan block totals
__device__ int   g_boff[NBLK];            // scan block offsets
// transposed bf16 weights: [layer][hi/lo][n*DIN + k], n in [0,160): Wl|Wr
__device__ __nv_bfloat16 g_wt[3][2][160 * 128];

// ---------------- bf16 split helpers -----------------------------------------
__device__ __forceinline__ void split_bf16(float f, __nv_bfloat16& hi, __nv_bfloat16& lo) {
    hi = __float2bfloat16(f);
    lo = __float2bfloat16(f - __bfloat162float(hi));
}

// HMMA m16n8k16 bf16 -> f32
__device__ __forceinline__ void mma16816(float* d, const u32* a, u32 b0, u32 b1) {
    asm volatile(
        "mma.sync.aligned.m16n8k16.row.col.f32.bf16.bf16.f32 "
        "{%0,%1,%2,%3}, {%4,%5,%6,%7}, {%8,%9}, {%0,%1,%2,%3};"
        : "+f"(d[0]), "+f"(d[1]), "+f"(d[2]), "+f"(d[3])
        : "r"(a[0]), "r"(a[1]), "r"(a[2]), "r"(a[3]), "r"(b0), "r"(b1));
}

// ---------------- W prep: fp32 [K][80] x2 -> k-major hi/lo bf16 [160][K] -----
__global__ void prep_w(const float* __restrict__ Wl, const float* __restrict__ Wr,
                       int K, int layer) {
    int t = blockIdx.x * blockDim.x + threadIdx.x;
    if (t >= 160 * K) return;
    int n = t / K, k = t - n * K;
    float v = (n < 80) ? Wl[k * 80 + n] : Wr[k * 80 + (n - 80)];
    __nv_bfloat16 hi, lo;
    split_bf16(v, hi, lo);
    g_wt[layer][0][n * K + k] = hi;
    g_wt[layer][1][n * K + k] = lo;
}

// ---------------- HMMA GEMM, split-output: CTA = 128 rows x 80 cols ----------
template <int DIN>
__global__ __launch_bounds__(256) void hmma_gemm(
    const float* __restrict__ X, int layer,
    float* __restrict__ Yl, float* __restrict__ Yr, int N) {
    constexpr int SA = DIN + 8;
    constexpr int KS = DIN / 16;
    extern __shared__ char smem[];
    __nv_bfloat16* Ah = (__nv_bfloat16*)smem;
    __nv_bfloat16* Al = Ah + 128 * SA;
    __nv_bfloat16* Bh = Al + 128 * SA;
    __nv_bfloat16* Bl = Bh + 80 * SA;

    const int tid = threadIdx.x;
    const int row0 = blockIdx.x * 128;
    const int half = blockIdx.y;            // 0 = Wl, 1 = Wr
    const int nglob0 = half * 80;

    for (int i = tid; i < 128 * (DIN / 4); i += 256) {
        int r = i / (DIN / 4), kq = i - r * (DIN / 4);
        int gr = row0 + r;
        float4 v = make_float4(0.f, 0.f, 0.f, 0.f);
        if (gr < N) v = *(const float4*)(X + (size_t)gr * DIN + kq * 4);
        __nv_bfloat16 h0, l0, h1, l1, h2, l2, h3, l3;
        split_bf16(v.x, h0, l0); split_bf16(v.y, h1, l1);
        split_bf16(v.z, h2, l2); split_bf16(v.w, h3, l3);
        __nv_bfloat16* ph = Ah + r * SA + kq * 4;
        __nv_bfloat16* pl = Al + r * SA + kq * 4;
        ph[0] = h0; ph[1] = h1; ph[2] = h2; ph[3] = h3;
        pl[0] = l0; pl[1] = l1; pl[2] = l2; pl[3] = l3;
    }
    for (int i = tid; i < 80 * (DIN / 4); i += 256) {
        int n = i / (DIN / 4), kq = i - n * (DIN / 4);
        uint2 vh = *(const uint2*)&g_wt[layer][0][(nglob0 + n) * DIN + kq * 4];
        uint2 vl = *(const uint2*)&g_wt[layer][1][(nglob0 + n) * DIN + kq * 4];
        *(uint2*)&Bh[n * SA + kq * 4] = vh;
        *(uint2*)&Bl[n * SA + kq * 4] = vl;
    }
    __syncthreads();

    const int warp = tid >> 5, lane = tid & 31;
    const int warpM = warp >> 1, warpN = warp & 1;
    const int r0 = warpM * 32, nbase = warpN * 40;
    const int g = lane >> 2, c = lane & 3;

    float acc[2][5][4];
#pragma unroll
    for (int mt = 0; mt < 2; mt++)
#pragma unroll
        for (int nt = 0; nt < 5; nt++)
#pragma unroll
            for (int q = 0; q < 4; q++) acc[mt][nt][q] = 0.f;

    for (int ks = 0; ks < KS; ks++) {
        const int kb = ks * 16;
        u32 ah[2][4], al[2][4];
#pragma unroll
        for (int mt = 0; mt < 2; mt++) {
            int base = (r0 + mt * 16 + g) * SA + kb;
            ah[mt][0] = *(const u32*)&Ah[base + 2 * c];
            ah[mt][1] = *(const u32*)&Ah[base + 8 * SA + 2 * c];
            ah[mt][2] = *(const u32*)&Ah[base + 2 * c + 8];
            ah[mt][3] = *(const u32*)&Ah[base + 8 * SA + 2 * c + 8];
            al[mt][0] = *(const u32*)&Al[base + 2 * c];
            al[mt][1] = *(const u32*)&Al[base + 8 * SA + 2 * c];
            al[mt][2] = *(const u32*)&Al[base + 2 * c + 8];
            al[mt][3] = *(const u32*)&Al[base + 8 * SA + 2 * c + 8];
        }
#pragma unroll
        for (int nt = 0; nt < 5; nt++) {
            int bbase = (nbase + nt * 8 + g) * SA + kb;
            u32 bh0 = *(const u32*)&Bh[bbase + 2 * c];
            u32 bh1 = *(const u32*)&Bh[bbase + 2 * c + 8];
            u32 bl0 = *(const u32*)&Bl[bbase + 2 * c];
            u32 bl1 = *(const u32*)&Bl[bbase + 2 * c + 8];
#pragma unroll
            for (int mt = 0; mt < 2; mt++) {
                mma16816(acc[mt][nt], ah[mt], bh0, bh1);
                mma16816(acc[mt][nt], ah[mt], bl0, bl1);
                mma16816(acc[mt][nt], al[mt], bh0, bh1);
            }
        }
    }

    float* Y = (half == 0) ? Yl : Yr;
#pragma unroll
    for (int mt = 0; mt < 2; mt++) {
        int ga = row0 + r0 + mt * 16 + g;
#pragma unroll
        for (int nt = 0; nt < 5; nt++) {
            int col = nbase + nt * 8 + 2 * c;
            if (ga < N)
                *(float2*)&Y[(size_t)ga * 80 + col] =
                    make_float2(acc[mt][nt][0], acc[mt][nt][1]);
            if (ga + 8 < N)
                *(float2*)&Y[(size_t)(ga + 8) * 80 + col] =
                    make_float2(acc[mt][nt][2], acc[mt][nt][3]);
        }
    }
}

// ---------------- CSR build (parallel 3-kernel scan) --------------------------
__global__ void hist_k(const int* __restrict__ ei) {
    int t = blockIdx.x * blockDim.x + threadIdx.x;
    if (t < EE) atomicAdd(&g_deg[ei[EE + t]], 1);
}

__global__ __launch_bounds__(1024) void pscan1_k() {
    __shared__ int warpsum[32];
    const int tid = threadIdx.x;
    const int lane = tid & 31, wid = tid >> 5;
    int i = blockIdx.x * 1024 + tid;
    int v = (i < NN) ? g_deg[i] : 0;
    int incl = v;
#pragma unroll
    for (int o = 1; o < 32; o <<= 1) {
        int n = __shfl_up_sync(0xffffffffu, incl, o);
        if (lane >= o) incl += n;
    }
    if (lane == 31) warpsum[wid] = incl;
    __syncthreads();
    if (tid < 32) {
        int w = warpsum[tid];
        int wi = w;
#pragma unroll
        for (int o = 1; o < 32; o <<= 1) {
            int n = __shfl_up_sync(0xffffffffu, wi, o);
            if (tid >= o) wi += n;
        }
        warpsum[tid] = wi - w;
    }
    __syncthreads();
    int excl = warpsum[wid] + incl - v;
    if (i < NN) g_rowptr[i] = excl;
    if (tid == 1023) g_bsum[blockIdx.x] = excl + v;
}

__global__ __launch_bounds__(128) void pscan2_k() {
    __shared__ int sh[NBLK];
    int tid = threadIdx.x;
    for (int i = tid; i < NBLK; i += 128) sh[i] = g_bsum[i];
    __syncthreads();
    if (tid == 0) {
        int run = 0;
        for (int i = 0; i < NBLK; i++) { int v = sh[i]; sh[i] = run; run += v; }
    }
    __syncthreads();
    for (int i = tid; i < NBLK; i += 128) g_boff[i] = sh[i];
}

__global__ __launch_bounds__(1024) void pscan3_k() {
    int i = blockIdx.x * 1024 + threadIdx.x;
    if (i < NN) {
        int r = g_rowptr[i] + g_boff[blockIdx.x];
        g_rowptr[i] = r;
        g_cursor[i] = r;
    }
    if (i == 0) g_rowptr[NN] = EE;
}

__global__ void fill_k(const int* __restrict__ ei) {
    int t = blockIdx.x * blockDim.x + threadIdx.x;
    if (t >= EE) return;
    int s = ei[t], d = ei[EE + t];
    int p = atomicAdd(&g_cursor[d], 1);
    g_csr[p] = s;
}

// ---------------- fused attention aggregate (fixed-shift, R13 loop shape) ----
// Fixed shift m = self-loop logit (validated: range << fp32 limits).
// Branch-free body, single-ahead register prefetch.
__global__ __launch_bounds__(256) void agg_k(const float* __restrict__ att,
                                             const float* __restrict__ bias,
                                             float* __restrict__ out) {
    int t = blockIdx.x * blockDim.x + threadIdx.x;
    if (t >= NN * H) return;
    int d = t >> 3, h = t & 7;

    float xr_[10], at[10];
    {
        const float2* xrp = (const float2*)(g_xr + (size_t)d * HC + h * C);
        const float2* atp = (const float2*)(att + h * C);
#pragma unroll
        for (int i = 0; i < 5; i++) {
            float2 a = __ldg(xrp + i);
            xr_[2 * i] = a.x; xr_[2 * i + 1] = a.y;
            float2 w = __ldg(atp + i);
            at[2 * i] = w.x; at[2 * i + 1] = w.y;
        }
    }

    // self loop defines the fixed shift m
    float acc[10];
    float m, ssum = 1.f;
    {
        const float2* xsp = (const float2*)(g_xl + (size_t)d * HC + h * C);
        float e = 0.f;
#pragma unroll
        for (int i = 0; i < 5; i++) {
            float2 a = __ldg(xsp + i);
            acc[2 * i] = a.x; acc[2 * i + 1] = a.y;
            float v0 = a.x + xr_[2 * i];     v0 = v0 > 0.f ? v0 : 0.2f * v0;
            float v1 = a.y + xr_[2 * i + 1]; v1 = v1 > 0.f ? v1 : 0.2f * v1;
            e += at[2 * i] * v0 + at[2 * i + 1] * v1;
        }
        m = e;
    }

    const int beg = __ldg(&g_rowptr[d]);
    const int end = __ldg(&g_rowptr[d + 1]);

    float nx[10];
    if (beg < end) {
        int s0 = __ldg(&g_csr[beg]);
        const float2* p = (const float2*)(g_xl + (size_t)s0 * HC + h * C);
#pragma unroll
        for (int i = 0; i < 5; i++) {
            float2 a = __ldg(p + i);
            nx[2 * i] = a.x; nx[2 * i + 1] = a.y;
        }
    }
    for (int j = beg; j < end; j++) {
        float xs_[10];
#pragma unroll
        for (int cc = 0; cc < 10; cc++) xs_[cc] = nx[cc];
        if (j + 1 < end) {
            int s2 = __ldg(&g_csr[j + 1]);
            const float2* p = (const float2*)(g_xl + (size_t)s2 * HC + h * C);
#pragma unroll
            for (int i = 0; i < 5; i++) {
                float2 a = __ldg(p + i);
                nx[2 * i] = a.x; nx[2 * i + 1] = a.y;
            }
        }
        float e = 0.f;
#pragma unroll
        for (int i = 0; i < 5; i++) {
            float v0 = xs_[2 * i] + xr_[2 * i];         v0 = v0 > 0.f ? v0 : 0.2f * v0;
            float v1 = xs_[2 * i + 1] + xr_[2 * i + 1]; v1 = v1 > 0.f ? v1 : 0.2f * v1;
            e += at[2 * i] * v0 + at[2 * i + 1] * v1;
        }
        float p = __expf(e - m);
        ssum += p;
#pragma unroll
        for (int cc = 0; cc < 10; cc++) acc[cc] = fmaf(p, xs_[cc], acc[cc]);
    }

    float inv = 1.f / ssum;
    float2* op = (float2*)(out + (size_t)d * HC + h * C);
#pragma unroll
    for (int i = 0; i < 5; i++) {
        float b0 = __ldg(bias + h * C + 2 * i);
        float b1 = __ldg(bias + h * C + 2 * i + 1);
        float v0 = acc[2 * i] * inv + b0;
        float v1 = acc[2 * i + 1] * inv + b1;
        v0 = v0 > 0.f ? v0 : expm1f(v0);
        v1 = v1 > 0.f ? v1 : expm1f(v1);
        op[i] = make_float2(v0, v1);
    }
}

// ---------------- launch -----------------------------------------------------
extern "C" void kernel_launch(void* const* d_in, const int* in_sizes, int n_in,
                              void* d_out, int out_size) {
    const float* x  = (const float*)d_in[0];
    const int*   ei = (const int*)d_in[1];
    const float* Wl[3]  = {(const float*)d_in[2], (const float*)d_in[6], (const float*)d_in[10]};
    const float* Wr[3]  = {(const float*)d_in[3], (const float*)d_in[7], (const float*)d_in[11]};
    const float* att[3] = {(const float*)d_in[4], (const float*)d_in[8], (const float*)d_in[12]};
    const float* bs[3]  = {(const float*)d_in[5], (const float*)d_in[9], (const float*)d_in[13]};

    const int N = NN;

    float *p_xl, *p_xr, *p_h;
    int* p_deg;
    cudaGetSymbolAddress((void**)&p_xl, g_xl);
    cudaGetSymbolAddress((void**)&p_xr, g_xr);
    cudaGetSymbolAddress((void**)&p_h, g_h);
    cudaGetSymbolAddress((void**)&p_deg, g_deg);

    // lazy host-side resources (same captured work every call)
    static cudaStream_t s2 = nullptr;
    static cudaEvent_t ev_fork = nullptr, ev_join = nullptr, ev_prep = nullptr;
    if (!s2) {
        cudaStreamCreateWithFlags(&s2, cudaStreamNonBlocking);
        cudaEventCreateWithFlags(&ev_fork, cudaEventDisableTiming);
        cudaEventCreateWithFlags(&ev_join, cudaEventDisableTiming);
        cudaEventCreateWithFlags(&ev_prep, cudaEventDisableTiming);
    }

    // ---- fork: CSR build + prep_w(1,2) on s2 ----
    cudaEventRecord(ev_fork, 0);
    cudaStreamWaitEvent(s2, ev_fork, 0);
    cudaMemsetAsync(p_deg, 0, (size_t)NN * sizeof(int), s2);
    hist_k<<<(EE + 255) / 256, 256, 0, s2>>>(ei);
    pscan1_k<<<NBLK, 1024, 0, s2>>>();
    pscan2_k<<<1, 128, 0, s2>>>();
    pscan3_k<<<NBLK, 1024, 0, s2>>>();
    fill_k<<<(EE + 255) / 256, 256, 0, s2>>>(ei);
    cudaEventRecord(ev_join, s2);
    prep_w<<<(160 * 80 + 255) / 256, 256, 0, s2>>>(Wl[1], Wr[1], 80, 1);
    prep_w<<<(160 * 80 + 255) / 256, 256, 0, s2>>>(Wl[2], Wr[2], 80, 2);
    cudaEventRecord(ev_prep, s2);

    // ---- main stream: layer-0 weight prep only ----
    prep_w<<<(160 * 128 + 255) / 256, 256>>>(Wl[0], Wr[0], 128, 0);

    const int smem128 = (2 * 128 + 2 * 80) * 136 * 2;  // 113152 -> 2 CTAs/SM
    const int smem80  = (2 * 128 + 2 * 80) * 88 * 2;   //  73216 -> 3 CTAs/SM
    cudaFuncSetAttribute(hmma_gemm<128>, cudaFuncAttributeMaxDynamicSharedMemorySize, smem128);
    cudaFuncSetAttribute(hmma_gemm<80>,  cudaFuncAttributeMaxDynamicSharedMemorySize, smem80);

    const dim3 gemmGrid((N + 127) / 128, 2);
    const int aggBlocks = (NN * H + 255) / 256;

    const float* xin = x;
    for (int l = 0; l < 3; l++) {
        if (l == 1) cudaStreamWaitEvent(0, ev_prep, 0);   // gemm1/2 need prep_w(1,2)
        if (l == 0)
            hmma_gemm<128><<<gemmGrid, 256, smem128>>>(xin, l, p_xl, p_xr, N);
        else
            hmma_gemm<80><<<gemmGrid, 256, smem80>>>(xin, l, p_xl, p_xr, N);
        if (l == 0) cudaStreamWaitEvent(0, ev_join, 0);   // agg needs CSR
        float* xout = (l == 2) ? (float*)d_out : p_h;
        agg_k<<<aggBlocks, 256>>>(att[l], bs[l], xout);
        xin = p_h;
    }
}